// round 1
// baseline (speedup 1.0000x reference)
#include <cuda_runtime.h>

#define TOK 8192
#define SEQ 2048
#define DIM 512
#define NH  8
#define HDM 64
#define NL  4
#define FF  200
#define NB  4

// ---------------- device scratch (allocation-free) ----------------
__device__ float g_x[TOK*DIM];
__device__ float g_q[TOK*DIM];
__device__ float g_k[TOK*DIM];
__device__ float g_v[TOK*DIM];
__device__ float g_y[TOK*DIM];
__device__ float g_t[TOK*DIM];
__device__ float g_h[TOK*FF];

// ---------------- positional encoding ----------------
__global__ void posenc_kernel(const float* __restrict__ f, float* __restrict__ x) {
    int idx = blockIdx.x * blockDim.x + threadIdx.x;
    if (idx >= TOK*DIM) return;
    int d = idx & (DIM-1);
    int s = (idx / DIM) & (SEQ-1);
    int i2 = d & ~1;  // 2*(d/2)
    float div = expf((float)i2 * (-9.210340371976184f / (float)DIM)); // -ln(10000)/D * 2i
    float ang = (float)s * div;
    float pe = (d & 1) ? cosf(ang) : sinf(ang);
    x[idx] = f[idx] + pe;
}

// ---------------- SGEMM: C[M,Nn] = A[M,K] @ B[K,Nn] + bias (+ReLU) ----------------
// 64x64 tile, KT=16, 256 threads (16x16), 4x4 per thread.
template<int RELU>
__global__ void gemm_bias_kernel(const float* __restrict__ A, const float* __restrict__ B,
                                 const float* __restrict__ bias, float* __restrict__ C,
                                 int M, int K, int Nn) {
    __shared__ float As[16][68];
    __shared__ float Bs[16][68];
    int tid = threadIdx.x;
    int tx = tid & 15, ty = tid >> 4;
    int m0 = blockIdx.y * 64, n0 = blockIdx.x * 64;

    float acc[4][4] = {};
    for (int k0 = 0; k0 < K; k0 += 16) {
        #pragma unroll
        for (int e = tid; e < 1024; e += 256) {
            int kk = e & 15, m = e >> 4;
            int gk = k0 + kk;
            As[kk][m] = (gk < K) ? A[(size_t)(m0 + m) * K + gk] : 0.f;
        }
        #pragma unroll
        for (int e = tid; e < 1024; e += 256) {
            int nn = e & 63, kk = e >> 6;
            int gk = k0 + kk, gn = n0 + nn;
            Bs[kk][nn] = (gk < K && gn < Nn) ? B[(size_t)gk * Nn + gn] : 0.f;
        }
        __syncthreads();
        #pragma unroll
        for (int kk = 0; kk < 16; kk++) {
            float a[4], b[4];
            #pragma unroll
            for (int i = 0; i < 4; i++) a[i] = As[kk][ty + i*16];
            #pragma unroll
            for (int j = 0; j < 4; j++) b[j] = Bs[kk][tx + j*16];
            #pragma unroll
            for (int i = 0; i < 4; i++)
                #pragma unroll
                for (int j = 0; j < 4; j++)
                    acc[i][j] = fmaf(a[i], b[j], acc[i][j]);
        }
        __syncthreads();
    }
    #pragma unroll
    for (int j = 0; j < 4; j++) {
        int gn = n0 + tx + j*16;
        if (gn >= Nn) continue;
        float bv = bias[gn];
        #pragma unroll
        for (int i = 0; i < 4; i++) {
            int gm = m0 + ty + i*16;
            float vv = acc[i][j] + bv;
            if (RELU) vv = fmaxf(vv, 0.f);
            C[(size_t)gm * Nn + gn] = vv;
        }
    }
}

// ---------------- flash attention ----------------
// grid: (SEQ/64, NH, NB); 256 threads; online softmax; BQ=BK=64, HD=64.
#define ATTN_SMEM (4 * 64 * 65 * 4)
__global__ void attn_kernel(const float* __restrict__ q, const float* __restrict__ k,
                            const float* __restrict__ v, float* __restrict__ y) {
    extern __shared__ float sm[];
    float* Qs = sm;              // [64][65]
    float* Ks = Qs + 64*65;
    float* Vs = Ks + 64*65;
    float* Ps = Vs + 64*65;

    int tid = threadIdx.x;
    int tx = tid & 15, ty = tid >> 4;
    int qt = blockIdx.x, h = blockIdx.y, n = blockIdx.z;
    const float scale = 0.125f;  // 1/sqrt(64)

    int qbase = n*SEQ + qt*64;
    for (int e = tid; e < 64*64; e += 256) {
        int d = e & 63, r = e >> 6;
        Qs[r*65 + d] = q[(size_t)(qbase + r) * DIM + h*HDM + d];
    }
    float O[4][4] = {};
    float mrow[4] = {-1e30f, -1e30f, -1e30f, -1e30f};
    float lrow[4] = {};
    __syncthreads();

    for (int kt = 0; kt < SEQ/64; kt++) {
        int kbase = n*SEQ + kt*64;
        for (int e = tid; e < 64*64; e += 256) {
            int d = e & 63, r = e >> 6;
            Ks[r*65 + d] = k[(size_t)(kbase + r) * DIM + h*HDM + d];
            Vs[r*65 + d] = v[(size_t)(kbase + r) * DIM + h*HDM + d];
        }
        __syncthreads();

        // S = scale * Q K^T  (4x4 per thread)
        float s[4][4] = {};
        #pragma unroll 8
        for (int d = 0; d < 64; d++) {
            float a[4], b[4];
            #pragma unroll
            for (int i = 0; i < 4; i++) a[i] = Qs[(ty + i*16)*65 + d];
            #pragma unroll
            for (int j = 0; j < 4; j++) b[j] = Ks[(tx + j*16)*65 + d];
            #pragma unroll
            for (int i = 0; i < 4; i++)
                #pragma unroll
                for (int j = 0; j < 4; j++)
                    s[i][j] = fmaf(a[i], b[j], s[i][j]);
        }

        // online softmax per row (16 lanes share a row; widths-16 xor reduce)
        #pragma unroll
        for (int i = 0; i < 4; i++) {
            #pragma unroll
            for (int j = 0; j < 4; j++) s[i][j] *= scale;
            float mloc = fmaxf(fmaxf(s[i][0], s[i][1]), fmaxf(s[i][2], s[i][3]));
            #pragma unroll
            for (int off = 8; off; off >>= 1)
                mloc = fmaxf(mloc, __shfl_xor_sync(0xffffffffu, mloc, off));
            float newm = fmaxf(mrow[i], mloc);
            float corr = expf(mrow[i] - newm);
            mrow[i] = newm;
            float rs = 0.f;
            #pragma unroll
            for (int j = 0; j < 4; j++) {
                s[i][j] = expf(s[i][j] - newm);
                rs += s[i][j];
            }
            #pragma unroll
            for (int off = 8; off; off >>= 1)
                rs += __shfl_xor_sync(0xffffffffu, rs, off);
            lrow[i] = lrow[i] * corr + rs;
            #pragma unroll
            for (int j = 0; j < 4; j++) {
                O[i][j] *= corr;
                Ps[(ty + i*16)*65 + tx + j*16] = s[i][j];
            }
        }
        __syncthreads();

        // O += P @ V
        #pragma unroll 8
        for (int c = 0; c < 64; c++) {
            float a[4], b[4];
            #pragma unroll
            for (int i = 0; i < 4; i++) a[i] = Ps[(ty + i*16)*65 + c];
            #pragma unroll
            for (int j = 0; j < 4; j++) b[j] = Vs[c*65 + tx + j*16];
            #pragma unroll
            for (int i = 0; i < 4; i++)
                #pragma unroll
                for (int j = 0; j < 4; j++)
                    O[i][j] = fmaf(a[i], b[j], O[i][j]);
        }
        __syncthreads();
    }

    #pragma unroll
    for (int i = 0; i < 4; i++) {
        float inv = 1.f / lrow[i];
        #pragma unroll
        for (int j = 0; j < 4; j++)
            y[(size_t)(qbase + ty + i*16) * DIM + h*HDM + tx + j*16] = O[i][j] * inv;
    }
}

// ---------------- fused residual + LayerNorm ----------------
// one block (128 thr) per token row of 512
__global__ void ln_kernel(const float* __restrict__ x, const float* __restrict__ r,
                          const float* __restrict__ w, const float* __restrict__ b,
                          float* __restrict__ out) {
    int row = blockIdx.x;
    int tid = threadIdx.x;
    const float* xr = x + (size_t)row * DIM;
    const float* rr = r + (size_t)row * DIM;
    float vals[4];
    float sum = 0.f;
    #pragma unroll
    for (int i = 0; i < 4; i++) {
        int d = tid + i*128;
        vals[i] = xr[d] + rr[d];
        sum += vals[i];
    }
    __shared__ float red1[4], red2[4];
    #pragma unroll
    for (int off = 16; off; off >>= 1) sum += __shfl_xor_sync(0xffffffffu, sum, off);
    if ((tid & 31) == 0) red1[tid >> 5] = sum;
    __syncthreads();
    sum = red1[0] + red1[1] + red1[2] + red1[3];
    float mean = sum * (1.f / DIM);
    float vs = 0.f;
    #pragma unroll
    for (int i = 0; i < 4; i++) {
        float dv = vals[i] - mean;
        vs += dv * dv;
    }
    #pragma unroll
    for (int off = 16; off; off >>= 1) vs += __shfl_xor_sync(0xffffffffu, vs, off);
    if ((tid & 31) == 0) red2[tid >> 5] = vs;
    __syncthreads();
    vs = red2[0] + red2[1] + red2[2] + red2[3];
    float rstd = rsqrtf(vs * (1.f / DIM) + 1e-5f);
    #pragma unroll
    for (int i = 0; i < 4; i++) {
        int d = tid + i*128;
        out[(size_t)row * DIM + d] = (vals[i] - mean) * rstd * w[d] + b[d];
    }
}

// ---------------- host ----------------
extern "C" void kernel_launch(void* const* d_in, const int* in_sizes, int n_in,
                              void* d_out, int out_size) {
    const float* features = (const float*)d_in[0];
    const float* Wq = (const float*)d_in[1];
    const float* bq = (const float*)d_in[2];
    const float* Wk = (const float*)d_in[3];
    const float* bk = (const float*)d_in[4];
    const float* Wv = (const float*)d_in[5];
    const float* bv = (const float*)d_in[6];
    const float* Wo = (const float*)d_in[7];
    const float* bo = (const float*)d_in[8];
    const float* W1 = (const float*)d_in[9];
    const float* b1 = (const float*)d_in[10];
    const float* W2 = (const float*)d_in[11];
    const float* b2 = (const float*)d_in[12];
    const float* ln1w = (const float*)d_in[13];
    const float* ln1b = (const float*)d_in[14];
    const float* ln2w = (const float*)d_in[15];
    const float* ln2b = (const float*)d_in[16];
    float* out = (float*)d_out;

    float *x, *q, *k, *v, *y, *t, *hbuf;
    cudaGetSymbolAddress((void**)&x, g_x);
    cudaGetSymbolAddress((void**)&q, g_q);
    cudaGetSymbolAddress((void**)&k, g_k);
    cudaGetSymbolAddress((void**)&v, g_v);
    cudaGetSymbolAddress((void**)&y, g_y);
    cudaGetSymbolAddress((void**)&t, g_t);
    cudaGetSymbolAddress((void**)&hbuf, g_h);

    cudaFuncSetAttribute(attn_kernel, cudaFuncAttributeMaxDynamicSharedMemorySize, ATTN_SMEM);

    posenc_kernel<<<(TOK*DIM + 255) / 256, 256>>>(features, x);

    dim3 gD(DIM/64, TOK/64);           // 512-col GEMMs
    dim3 gF((FF + 63) / 64, TOK/64);   // 200-col GEMM
    dim3 gA(SEQ/64, NH, NB);

    for (int l = 0; l < NL; l++) {
        gemm_bias_kernel<0><<<gD, 256>>>(x, Wq + (size_t)l*DIM*DIM, bq + l*DIM, q, TOK, DIM, DIM);
        gemm_bias_kernel<0><<<gD, 256>>>(x, Wk + (size_t)l*DIM*DIM, bk + l*DIM, k, TOK, DIM, DIM);
        gemm_bias_kernel<0><<<gD, 256>>>(x, Wv + (size_t)l*DIM*DIM, bv + l*DIM, v, TOK, DIM, DIM);
        attn_kernel<<<gA, 256, ATTN_SMEM>>>(q, k, v, y);
        gemm_bias_kernel<0><<<gD, 256>>>(y, Wo + (size_t)l*DIM*DIM, bo + l*DIM, t, TOK, DIM, DIM);
        ln_kernel<<<TOK, 128>>>(x, t, ln1w + l*DIM, ln1b + l*DIM, x);
        gemm_bias_kernel<1><<<gF, 256>>>(x, W1 + (size_t)l*DIM*FF, b1 + l*FF, hbuf, TOK, DIM, FF);
        gemm_bias_kernel<0><<<gD, 256>>>(hbuf, W2 + (size_t)l*FF*DIM, b2 + l*DIM, t, TOK, FF, DIM);
        float* lnout = (l == NL-1) ? out : x;
        ln_kernel<<<TOK, 128>>>(x, t, ln2w + l*DIM, ln2b + l*DIM, lnout);
    }
}

// round 2
// speedup vs baseline: 1.4861x; 1.4861x over previous
#include <cuda_runtime.h>

#define TOK 8192
#define SEQ 2048
#define DIM 512
#define NH  8
#define HDM 64
#define NL  4
#define FF  200
#define NB  4

// ---------------- device scratch (allocation-free) ----------------
__device__ float g_x[TOK*DIM];
__device__ float g_q[TOK*DIM];
__device__ float g_k[TOK*DIM];
__device__ float g_v[TOK*DIM];
__device__ float g_y[TOK*DIM];
__device__ float g_t[TOK*DIM];
__device__ float g_h[TOK*FF];

// ---------------- fast exp2 on the FMA pipe (input <= 0, underflow->0) ------
__device__ __forceinline__ float exp2_fast(float t) {
    t = fmaxf(t, -126.0f);
    float z = t + 12582912.0f;              // 1.5*2^23: round-to-nearest-int trick
    int   ii = __float_as_int(z);
    float n  = z - 12582912.0f;
    float f  = t - n;                       // f in [-0.5, 0.5]
    float p  =            1.535336188319500e-4f;
    p = fmaf(p, f, 1.339887440266574e-3f);
    p = fmaf(p, f, 9.618437357674640e-3f);
    p = fmaf(p, f, 5.550332471162809e-2f);
    p = fmaf(p, f, 2.402264791363012e-1f);
    p = fmaf(p, f, 6.931472028550421e-1f);
    p = fmaf(p, f, 1.0f);
    return __int_as_float(__float_as_int(p) + (ii << 23));   // p * 2^n
}

// ---------------- positional encoding ----------------
__global__ void posenc_kernel(const float* __restrict__ f, float* __restrict__ x) {
    int idx = blockIdx.x * blockDim.x + threadIdx.x;
    if (idx >= TOK*DIM) return;
    int d = idx & (DIM-1);
    int s = (idx / DIM) & (SEQ-1);
    int i2 = d & ~1;
    float div = expf((float)i2 * (-9.210340371976184f / (float)DIM));
    float ang = (float)s * div;
    float pe = (d & 1) ? cosf(ang) : sinf(ang);
    x[idx] = f[idx] + pe;
}

// ---------------- SGEMM 128x128x8, 8x8 per thread, float4 everywhere -------
template<int RELU>
__global__ __launch_bounds__(256, 2)
void gemm128_kernel(const float* __restrict__ A, const float* __restrict__ B,
                    const float* __restrict__ bias, float* __restrict__ C,
                    int M, int K, int Nn) {
    __shared__ float As[8][128];   // A^T tile
    __shared__ float Bs[8][128];
    int tid = threadIdx.x;
    int tx = tid & 15, ty = tid >> 4;
    int m0 = blockIdx.y * 128, n0 = blockIdx.x * 128;

    // load indices
    int a_row = tid >> 1;                // 0..127
    int a_kg  = (tid & 1) * 4;           // 0 or 4
    int b_k   = tid >> 5;                // 0..7
    int b_col = (tid & 31) * 4;          // 0..124

    float acc[8][8] = {};

    for (int k0 = 0; k0 < K; k0 += 8) {
        // A tile: rows m0..+127, cols k0..+7 (K always %8==0 here)
        float4 av = *(const float4*)&A[(size_t)(m0 + a_row) * K + k0 + a_kg];
        // B tile: row k0+b_k, cols n0+b_col..+3 (guard N)
        float4 bv;
        int gn = n0 + b_col;
        if (gn + 3 < Nn) {
            bv = *(const float4*)&B[(size_t)(k0 + b_k) * Nn + gn];
        } else {
            const float* br = &B[(size_t)(k0 + b_k) * Nn];
            bv.x = (gn + 0 < Nn) ? br[gn + 0] : 0.f;
            bv.y = (gn + 1 < Nn) ? br[gn + 1] : 0.f;
            bv.z = (gn + 2 < Nn) ? br[gn + 2] : 0.f;
            bv.w = (gn + 3 < Nn) ? br[gn + 3] : 0.f;
        }
        As[a_kg + 0][a_row] = av.x;
        As[a_kg + 1][a_row] = av.y;
        As[a_kg + 2][a_row] = av.z;
        As[a_kg + 3][a_row] = av.w;
        *(float4*)&Bs[b_k][b_col] = bv;
        __syncthreads();

        #pragma unroll
        for (int k = 0; k < 8; k++) {
            float4 a0 = *(const float4*)&As[k][ty * 4];
            float4 a1 = *(const float4*)&As[k][64 + ty * 4];
            float4 b0 = *(const float4*)&Bs[k][tx * 4];
            float4 b1 = *(const float4*)&Bs[k][64 + tx * 4];
            float ar[8] = {a0.x, a0.y, a0.z, a0.w, a1.x, a1.y, a1.z, a1.w};
            float br[8] = {b0.x, b0.y, b0.z, b0.w, b1.x, b1.y, b1.z, b1.w};
            #pragma unroll
            for (int i = 0; i < 8; i++)
                #pragma unroll
                for (int j = 0; j < 8; j++)
                    acc[i][j] = fmaf(ar[i], br[j], acc[i][j]);
        }
        __syncthreads();
    }

    // epilogue
    #pragma unroll
    for (int i = 0; i < 8; i++) {
        int gm = m0 + ((i < 4) ? (ty * 4 + i) : (64 + ty * 4 + i - 4));
        #pragma unroll
        for (int j = 0; j < 8; j++) {
            int gn = n0 + ((j < 4) ? (tx * 4 + j) : (64 + tx * 4 + j - 4));
            if (gn < Nn) {
                float vv = acc[i][j] + bias[gn];
                if (RELU) vv = fmaxf(vv, 0.f);
                C[(size_t)gm * Nn + gn] = vv;
            }
        }
    }
}

// ---------------- flash attention: BQ=128, BK=64, 8x4 per thread -----------
// smem: Qt[64][132] (Q^T), Kt[64][68] (K^T), Vs[64][68], Pt[64][132] (P^T)
#define QT_STRIDE 132
#define KT_STRIDE 68
#define ATTN_SMEM ((64*132 + 64*68 + 64*68 + 64*132) * 4)

__global__ __launch_bounds__(256)
void attn_kernel(const float* __restrict__ q, const float* __restrict__ k,
                 const float* __restrict__ v, float* __restrict__ y) {
    extern __shared__ float sm[];
    float* Qt = sm;                          // [d][row]  64 x 132
    float* Kt = Qt + 64 * QT_STRIDE;         // [d][col]  64 x 68
    float* Vs = Kt + 64 * KT_STRIDE;         // [c][d]    64 x 68
    float* Pt = Vs + 64 * KT_STRIDE;         // [c][row]  64 x 132

    int tid = threadIdx.x;
    int tx = tid & 15, ty = tid >> 4;
    int qt_blk = blockIdx.x, h = blockIdx.y, n = blockIdx.z;
    const float SCALE_LOG2E = 0.125f * 1.4426950408889634f;

    int qbase = n * SEQ + qt_blk * 128;
    int hoff = h * HDM;

    // load Q tile transposed: Qt[d][row]
    #pragma unroll
    for (int it = 0; it < 8; it++) {
        int idx4 = tid + it * 256;           // over 128*16 float4 slots
        int row = idx4 >> 4;
        int d = (idx4 & 15) * 4;
        float4 qv = *(const float4*)&q[(size_t)(qbase + row) * DIM + hoff + d];
        Qt[(d + 0) * QT_STRIDE + row] = qv.x;
        Qt[(d + 1) * QT_STRIDE + row] = qv.y;
        Qt[(d + 2) * QT_STRIDE + row] = qv.z;
        Qt[(d + 3) * QT_STRIDE + row] = qv.w;
    }

    float O[8][4] = {};
    float mrow[8];
    float lrow[8] = {};
    #pragma unroll
    for (int i = 0; i < 8; i++) mrow[i] = -1e30f;
    __syncthreads();

    for (int kt = 0; kt < SEQ / 64; kt++) {
        int kbase = n * SEQ + kt * 64;
        // load K transposed + V natural
        #pragma unroll
        for (int it = 0; it < 4; it++) {
            int idx4 = tid + it * 256;       // over 64*16 slots
            int r = idx4 >> 4;
            int d = (idx4 & 15) * 4;
            float4 kv = *(const float4*)&k[(size_t)(kbase + r) * DIM + hoff + d];
            Kt[(d + 0) * KT_STRIDE + r] = kv.x;
            Kt[(d + 1) * KT_STRIDE + r] = kv.y;
            Kt[(d + 2) * KT_STRIDE + r] = kv.z;
            Kt[(d + 3) * KT_STRIDE + r] = kv.w;
            float4 vv = *(const float4*)&v[(size_t)(kbase + r) * DIM + hoff + d];
            *(float4*)&Vs[r * KT_STRIDE + d] = vv;
        }
        __syncthreads();

        // S = Q K^T   (rows ty*8+i, cols tx*4+j)
        float s[8][4] = {};
        #pragma unroll
        for (int d = 0; d < 64; d++) {
            float4 a0 = *(const float4*)&Qt[d * QT_STRIDE + ty * 8];
            float4 a1 = *(const float4*)&Qt[d * QT_STRIDE + ty * 8 + 4];
            float4 b  = *(const float4*)&Kt[d * KT_STRIDE + tx * 4];
            float ar[8] = {a0.x, a0.y, a0.z, a0.w, a1.x, a1.y, a1.z, a1.w};
            float br[4] = {b.x, b.y, b.z, b.w};
            #pragma unroll
            for (int i = 0; i < 8; i++)
                #pragma unroll
                for (int j = 0; j < 4; j++)
                    s[i][j] = fmaf(ar[i], br[j], s[i][j]);
        }

        // online softmax in base-2 domain; 16 lanes (tx) share a row
        #pragma unroll
        for (int i = 0; i < 8; i++) {
            float t0 = s[i][0] * SCALE_LOG2E;
            float t1 = s[i][1] * SCALE_LOG2E;
            float t2 = s[i][2] * SCALE_LOG2E;
            float t3 = s[i][3] * SCALE_LOG2E;
            float mloc = fmaxf(fmaxf(t0, t1), fmaxf(t2, t3));
            #pragma unroll
            for (int off = 8; off; off >>= 1)
                mloc = fmaxf(mloc, __shfl_xor_sync(0xffffffffu, mloc, off));
            float newm = fmaxf(mrow[i], mloc);
            float corr = exp2_fast(mrow[i] - newm);
            mrow[i] = newm;
            float p0 = exp2_fast(t0 - newm);
            float p1 = exp2_fast(t1 - newm);
            float p2 = exp2_fast(t2 - newm);
            float p3 = exp2_fast(t3 - newm);
            float rs = (p0 + p1) + (p2 + p3);
            #pragma unroll
            for (int off = 8; off; off >>= 1)
                rs += __shfl_xor_sync(0xffffffffu, rs, off);
            lrow[i] = lrow[i] * corr + rs;
            #pragma unroll
            for (int j = 0; j < 4; j++) O[i][j] *= corr;
            s[i][0] = p0; s[i][1] = p1; s[i][2] = p2; s[i][3] = p3;
        }

        // store P transposed: Pt[c][row]
        #pragma unroll
        for (int j = 0; j < 4; j++) {
            int c = tx * 4 + j;
            float4 p0 = make_float4(s[0][j], s[1][j], s[2][j], s[3][j]);
            float4 p1 = make_float4(s[4][j], s[5][j], s[6][j], s[7][j]);
            *(float4*)&Pt[c * QT_STRIDE + ty * 8] = p0;
            *(float4*)&Pt[c * QT_STRIDE + ty * 8 + 4] = p1;
        }
        __syncthreads();

        // O += P V   (sum over c)
        #pragma unroll
        for (int c = 0; c < 64; c++) {
            float4 a0 = *(const float4*)&Pt[c * QT_STRIDE + ty * 8];
            float4 a1 = *(const float4*)&Pt[c * QT_STRIDE + ty * 8 + 4];
            float4 b  = *(const float4*)&Vs[c * KT_STRIDE + tx * 4];
            float ar[8] = {a0.x, a0.y, a0.z, a0.w, a1.x, a1.y, a1.z, a1.w};
            float br[4] = {b.x, b.y, b.z, b.w};
            #pragma unroll
            for (int i = 0; i < 8; i++)
                #pragma unroll
                for (int j = 0; j < 4; j++)
                    O[i][j] = fmaf(ar[i], br[j], O[i][j]);
        }
        __syncthreads();
    }

    // write out normalized
    #pragma unroll
    for (int i = 0; i < 8; i++) {
        float inv = 1.0f / lrow[i];
        int row = qbase + ty * 8 + i;
        float4 ov = make_float4(O[i][0] * inv, O[i][1] * inv, O[i][2] * inv, O[i][3] * inv);
        *(float4*)&y[(size_t)row * DIM + hoff + tx * 4] = ov;
    }
}

// ---------------- fused residual + LayerNorm ----------------
__global__ void ln_kernel(const float* __restrict__ x, const float* __restrict__ r,
                          const float* __restrict__ w, const float* __restrict__ b,
                          float* __restrict__ out) {
    int row = blockIdx.x;
    int tid = threadIdx.x;
    const float* xr = x + (size_t)row * DIM;
    const float* rr = r + (size_t)row * DIM;
    float vals[4];
    float sum = 0.f;
    #pragma unroll
    for (int i = 0; i < 4; i++) {
        int d = tid + i*128;
        vals[i] = xr[d] + rr[d];
        sum += vals[i];
    }
    __shared__ float red1[4], red2[4];
    #pragma unroll
    for (int off = 16; off; off >>= 1) sum += __shfl_xor_sync(0xffffffffu, sum, off);
    if ((tid & 31) == 0) red1[tid >> 5] = sum;
    __syncthreads();
    sum = red1[0] + red1[1] + red1[2] + red1[3];
    float mean = sum * (1.f / DIM);
    float vs = 0.f;
    #pragma unroll
    for (int i = 0; i < 4; i++) {
        float dv = vals[i] - mean;
        vs += dv * dv;
    }
    #pragma unroll
    for (int off = 16; off; off >>= 1) vs += __shfl_xor_sync(0xffffffffu, vs, off);
    if ((tid & 31) == 0) red2[tid >> 5] = vs;
    __syncthreads();
    vs = red2[0] + red2[1] + red2[2] + red2[3];
    float rstd = rsqrtf(vs * (1.f / DIM) + 1e-5f);
    #pragma unroll
    for (int i = 0; i < 4; i++) {
        int d = tid + i*128;
        out[(size_t)row * DIM + d] = (vals[i] - mean) * rstd * w[d] + b[d];
    }
}

// ---------------- host ----------------
extern "C" void kernel_launch(void* const* d_in, const int* in_sizes, int n_in,
                              void* d_out, int out_size) {
    const float* features = (const float*)d_in[0];
    const float* Wq = (const float*)d_in[1];
    const float* bq = (const float*)d_in[2];
    const float* Wk = (const float*)d_in[3];
    const float* bk = (const float*)d_in[4];
    const float* Wv = (const float*)d_in[5];
    const float* bv = (const float*)d_in[6];
    const float* Wo = (const float*)d_in[7];
    const float* bo = (const float*)d_in[8];
    const float* W1 = (const float*)d_in[9];
    const float* b1 = (const float*)d_in[10];
    const float* W2 = (const float*)d_in[11];
    const float* b2 = (const float*)d_in[12];
    const float* ln1w = (const float*)d_in[13];
    const float* ln1b = (const float*)d_in[14];
    const float* ln2w = (const float*)d_in[15];
    const float* ln2b = (const float*)d_in[16];
    float* out = (float*)d_out;

    float *x, *q, *k, *v, *y, *t, *hbuf;
    cudaGetSymbolAddress((void**)&x, g_x);
    cudaGetSymbolAddress((void**)&q, g_q);
    cudaGetSymbolAddress((void**)&k, g_k);
    cudaGetSymbolAddress((void**)&v, g_v);
    cudaGetSymbolAddress((void**)&y, g_y);
    cudaGetSymbolAddress((void**)&t, g_t);
    cudaGetSymbolAddress((void**)&hbuf, g_h);

    cudaFuncSetAttribute(attn_kernel, cudaFuncAttributeMaxDynamicSharedMemorySize, ATTN_SMEM);

    posenc_kernel<<<(TOK*DIM + 255) / 256, 256>>>(features, x);

    dim3 gD(DIM/128, TOK/128);                 // 512-col GEMMs: (4,64)
    dim3 gF((FF + 127) / 128, TOK/128);        // 200-col GEMM:  (2,64)
    dim3 gA(SEQ/128, NH, NB);                  // attention:     (16,8,4)

    for (int l = 0; l < NL; l++) {
        gemm128_kernel<0><<<gD, 256>>>(x, Wq + (size_t)l*DIM*DIM, bq + l*DIM, q, TOK, DIM, DIM);
        gemm128_kernel<0><<<gD, 256>>>(x, Wk + (size_t)l*DIM*DIM, bk + l*DIM, k, TOK, DIM, DIM);
        gemm128_kernel<0><<<gD, 256>>>(x, Wv + (size_t)l*DIM*DIM, bv + l*DIM, v, TOK, DIM, DIM);
        attn_kernel<<<gA, 256, ATTN_SMEM>>>(q, k, v, y);
        gemm128_kernel<0><<<gD, 256>>>(y, Wo + (size_t)l*DIM*DIM, bo + l*DIM, t, TOK, DIM, DIM);
        ln_kernel<<<TOK, 128>>>(x, t, ln1w + l*DIM, ln1b + l*DIM, x);
        gemm128_kernel<1><<<gF, 256>>>(x, W1 + (size_t)l*DIM*FF, b1 + l*FF, hbuf, TOK, DIM, FF);
        gemm128_kernel<0><<<gD, 256>>>(hbuf, W2 + (size_t)l*FF*DIM, b2 + l*DIM, t, TOK, FF, DIM);
        float* lnout = (l == NL-1) ? out : x;
        ln_kernel<<<TOK, 128>>>(x, t, ln2w + l*DIM, ln2b + l*DIM, lnout);
    }
}